// round 14
// baseline (speedup 1.0000x reference)
#include <cuda_runtime.h>

#define H 2048
#define WD 2048
#define WORDS 32   // 2048 bits / 64 per lane
#define NR 16      // rows per block
#define GRID 128   // blocks: block blk owns rows 16*blk .. 16*blk+15 (oe = 1)
#define NC GRID    // chunk c = rows [16c, 16c+16) ∩ [1, H-2]

typedef unsigned long long ull;

// ---- persistent device scratch (no allocation allowed) ----
__device__ unsigned g_maxbits;            // zero at load; atomicMax idempotent per input
__device__ unsigned g_tick;               // last-block ticket; reset to 0 each launch by last block
__device__ unsigned g_bar;                // max-phase barrier counter; reset to 0 each launch by last block
__device__ ull g_S0[WORDS];               // strong mask of t, row 0 (passB seed)
__device__ ulonglong2 g_AW[H * WORDS];    // interleaved {a0, weak} for passB
__device__ ull g_O[H * WORDS];            // new strong masks (rows 1..H-2), passB seeds/fixup
__device__ int g_conv[NC];                // first converged row per chunk

__device__ __forceinline__ unsigned enc(float f) {
    unsigned u = __float_as_uint(f);
    return (u & 0x80000000u) ? ~u : (u | 0x80000000u);
}
__device__ __forceinline__ float dec(unsigned u) {
    u = (u & 0x80000000u) ? (u & 0x7FFFFFFFu) : ~u;
    return __uint_as_float(u);
}

// One row-update step (warp-collective). b must already be interior-masked.
__device__ __forceinline__ ull row_step(ull s_prev, ull a0, ull b, int lane) {
    ull su = __shfl_up_sync(0xFFFFFFFFu, s_prev, 1);   if (lane == 0)  su = 0;
    ull sd = __shfl_down_sync(0xFFFFFFFFu, s_prev, 1); if (lane == 31) sd = 0;
    ull spread = s_prev | (s_prev << 1) | (su >> 63) | (s_prev >> 1) | (sd << 63);
    ull a = a0 | (b & spread);
    ull X = a | b;
    ull S0 = X + a;
    ull S1 = S0 + 1;
    bool Gw = S0 < X;
    bool Pw = (S0 == ~0ULL);
    unsigned gg = __ballot_sync(0xFFFFFFFFu, Gw);
    unsigned pp = __ballot_sync(0xFFFFFFFFu, Pw);
    ull c0 = S0 ^ X ^ a;
    ull c1 = S1 ^ X ^ a;
    ull out0 = (c0 >> 1) | ((ull)Gw << 63);
    ull out1 = (c1 >> 1) | ((ull)(Gw | Pw) << 63);
    unsigned Xr = gg | pp;
    unsigned Sr = Xr + gg;
    unsigned cr = Sr ^ Xr ^ gg;             // bit w = carry INTO word w
    unsigned cin = (cr >> lane) & 1u;
    return cin ? out1 : out0;
}

// Expand a 4-bit strong/weak nibble pair into a float4.
__device__ __forceinline__ float4 nib2f4(unsigned snib, unsigned wnib) {
    float4 v;
    v.x = (snib & 1u) ? 255.0f : ((wnib & 1u) ? 25.0f : 0.0f);
    v.y = (snib & 2u) ? 255.0f : ((wnib & 2u) ? 25.0f : 0.0f);
    v.z = (snib & 4u) ? 255.0f : ((wnib & 4u) ? 25.0f : 0.0f);
    v.w = (snib & 8u) ? 255.0f : ((wnib & 8u) ? 25.0f : 0.0f);
    return v;
}

// Single fused kernel, one CTA per SM.
__global__ void __launch_bounds__(256) k_all(const float* __restrict__ x,
                                             float* __restrict__ out) {
    __shared__ ull sS[(NR + 2) * 32];  // sS[0]=row r0-1, sS[1+lr]=row r0+lr, sS[NR+1]=row r0+NR
    __shared__ ull sW[(NR + 1) * 32];  // sW[0]=row r0-1, sW[1+lr]=row r0+lr
    __shared__ ull sA[NR * 32];        // A0 of rows r0..r0+NR-1
    __shared__ ull sO[NR * 32];        // lo chain (speculative new strong)
    __shared__ ull sHi[NR * 32];       // hi chain
    __shared__ unsigned char sEq[NR];  // per-row lo==hi flags
    __shared__ float sred[8];
    __shared__ unsigned s_last;
    const int tid = threadIdx.x;
    const int w = tid >> 5;
    const int lane = tid & 31;
    const int blk = blockIdx.x;
    const int r0 = blk * NR;

    // ---- phase 0: coalesced DRAM read + block max + grid barrier ----
    {
        const float4* x4 = (const float4*)x + (size_t)blk * (NR * WD / 4);  // 8192 float4
        float m0 = 0.0f, m1 = 0.0f, m2 = 0.0f, m3 = 0.0f;                   // inputs uniform [0,1)
        #pragma unroll
        for (int it = 0; it < 8; ++it) {
            float4 v0 = x4[tid + (it * 4 + 0) * 256];
            float4 v1 = x4[tid + (it * 4 + 1) * 256];
            float4 v2 = x4[tid + (it * 4 + 2) * 256];
            float4 v3 = x4[tid + (it * 4 + 3) * 256];
            m0 = fmaxf(m0, fmaxf(fmaxf(v0.x, v0.y), fmaxf(v0.z, v0.w)));
            m1 = fmaxf(m1, fmaxf(fmaxf(v1.x, v1.y), fmaxf(v1.z, v1.w)));
            m2 = fmaxf(m2, fmaxf(fmaxf(v2.x, v2.y), fmaxf(v2.z, v2.w)));
            m3 = fmaxf(m3, fmaxf(fmaxf(v3.x, v3.y), fmaxf(v3.z, v3.w)));
        }
        float m = fmaxf(fmaxf(m0, m1), fmaxf(m2, m3));
        #pragma unroll
        for (int o = 16; o > 0; o >>= 1)
            m = fmaxf(m, __shfl_xor_sync(0xFFFFFFFFu, m, o));
        if (lane == 0) sred[w] = m;
        __syncthreads();
        if (tid == 0) {
            float mm = sred[0];
            #pragma unroll
            for (int k = 1; k < 8; ++k) mm = fmaxf(mm, sred[k]);
            atomicMax(&g_maxbits, enc(mm));
            __threadfence();
            atomicAdd(&g_bar, 1u);
            unsigned v;
            do {
                asm volatile("ld.acquire.gpu.global.u32 %0, [%1];" : "=r"(v) : "l"(&g_bar) : "memory");
                if (v >= GRID) break;
                __nanosleep(32);
            } while (true);
            unsigned mb;
            asm volatile("ld.acquire.gpu.global.u32 %0, [%1];" : "=r"(mb) : "l"(&g_maxbits) : "memory");
            sred[0] = dec(mb);
        }
        __syncthreads();
    }
    const float high = sred[0] * 0.15f;
    const float low = high * 0.05f;

    // ---- mask phase: warp w -> rows 2w, 2w+1 (ballot-built words; L2-hot) ----
    {
        #pragma unroll
        for (int rr = 0; rr < 2; ++rr) {
            int lr = 2 * w + rr;
            int r = r0 + lr;
            const float* rowp = x + (size_t)r * WD;
            for (int wd = 0; wd < 32; ++wd) {
                float a = rowp[wd * 64 + lane];
                float b2 = rowp[wd * 64 + 32 + lane];
                unsigned slo = __ballot_sync(0xFFFFFFFFu, a > high);
                unsigned shi = __ballot_sync(0xFFFFFFFFu, b2 > high);
                unsigned wlo = __ballot_sync(0xFFFFFFFFu, (a >= low) && (a <= high));
                unsigned whi = __ballot_sync(0xFFFFFFFFu, (b2 >= low) && (b2 <= high));
                if (lane == 0) {
                    ull S = (ull)slo | ((ull)shi << 32);
                    ull Wm = (ull)wlo | ((ull)whi << 32);
                    sS[(1 + lr) * 32 + wd] = S;
                    sW[(1 + lr) * 32 + wd] = Wm;
                    if (r == 0) g_S0[wd] = S;      // passB seed (block 0 only)
                }
            }
        }
        if (blk > 0 && w < 4) {                    // boundary row r0-1: S and W
            const float* rm = x + (size_t)(r0 - 1) * WD;
            #pragma unroll
            for (int j = 0; j < 8; ++j) {
                int wd = w * 8 + j;
                float a = rm[wd * 64 + lane];
                float b2 = rm[wd * 64 + 32 + lane];
                unsigned slo = __ballot_sync(0xFFFFFFFFu, a > high);
                unsigned shi = __ballot_sync(0xFFFFFFFFu, b2 > high);
                unsigned wlo = __ballot_sync(0xFFFFFFFFu, (a >= low) && (a <= high));
                unsigned whi = __ballot_sync(0xFFFFFFFFu, (b2 >= low) && (b2 <= high));
                if (lane == 0) {
                    sS[wd] = (ull)slo | ((ull)shi << 32);
                    sW[wd] = (ull)wlo | ((ull)whi << 32);
                }
            }
        }
        if (blk < GRID - 1 && w >= 4) {            // boundary row r0+NR: S only
            const float* rp = x + (size_t)(r0 + NR) * WD;
            #pragma unroll
            for (int j = 0; j < 8; ++j) {
                int wd = (w - 4) * 8 + j;
                float a = rp[wd * 64 + lane];
                float b2 = rp[wd * 64 + 32 + lane];
                unsigned slo = __ballot_sync(0xFFFFFFFFu, a > high);
                unsigned shi = __ballot_sync(0xFFFFFFFFu, b2 > high);
                if (lane == 0) sS[(NR + 1) * 32 + wd] = (ull)slo | ((ull)shi << 32);
            }
        }
    }
    __syncthreads();

    // ---- A0 phase: warp w -> rows 2w, 2w+1 (interior only) ----
    {
        #pragma unroll
        for (int rr = 0; rr < 2; ++rr) {
            int lr = 2 * w + rr;
            int i = r0 + lr;
            if (i >= 1 && i <= H - 2) {
                ull cs = sS[(1 + lr) * 32 + lane];
                ull ns = sS[(2 + lr) * 32 + lane];
                ull wk = sW[(1 + lr) * 32 + lane];
                ull wkI = wk;
                if (lane == 0)  wkI &= ~1ULL;
                if (lane == 31) wkI &= 0x7FFFFFFFFFFFFFFFULL;
                ull cs_n = __shfl_down_sync(0xFFFFFFFFu, cs, 1); if (lane == 31) cs_n = 0;
                ull ns_n = __shfl_down_sync(0xFFFFFFFFu, ns, 1); if (lane == 31) ns_n = 0;
                ull ns_p = __shfl_up_sync(0xFFFFFFFFu, ns, 1);   if (lane == 0)  ns_p = 0;
                ull shl_cs = (cs >> 1) | (cs_n << 63);
                ull shl_ns = (ns >> 1) | (ns_n << 63);
                ull shr_ns = (ns << 1) | (ns_p >> 63);
                ull base0 = shl_cs | shr_ns | ns | shl_ns;
                ull a0v = cs | (wkI & base0);
                sA[lr * 32 + lane] = a0v;
                ulonglong2 v; v.x = a0v; v.y = wk;
                g_AW[i * WORDS + lane] = v;
            }
        }
    }
    __syncthreads();

    ull bclear = ~0ULL;
    if (lane == 0)  bclear = ~1ULL;
    if (lane == 31) bclear = 0x7FFFFFFFFFFFFFFFULL;

    const int rstart = (blk == 0) ? 1 : r0;
    const int rend = min(r0 + NR, H - 1);

    // ---- passA: lo chain in warp 0, hi chain in warp 1 (independent) ----
    if (w <= 1) {
        bool isLo = (w == 0);
        ull s;
        if (blk == 0) s = sS[32 + lane];                             // row 0 exact
        else s = isLo ? sS[lane] : (sS[lane] | (sW[lane] & bclear)); // bounds of row r0-1
        #pragma unroll 1
        for (int i = rstart; i < rend; ++i) {
            ull a0 = sA[(i - r0) * 32 + lane];
            ull b = sW[(1 + i - r0) * 32 + lane] & bclear;
            s = row_step(s, a0, b, lane);
            if (isLo) {
                sO[(i - r0) * 32 + lane] = s;
                g_O[i * WORDS + lane] = s;
            } else {
                sHi[(i - r0) * 32 + lane] = s;
            }
        }
    }
    __syncthreads();

    // ---- conv detection: warp w checks rows 2w, 2w+1; warp 0 reduces ----
    {
        #pragma unroll
        for (int rr = 0; rr < 2; ++rr) {
            int lr = 2 * w + rr;
            int i = r0 + lr;
            bool valid = (i >= rstart) && (i < rend);
            ull lov = sO[lr * 32 + lane];
            ull hiv = sHi[lr * 32 + lane];
            unsigned ne = __ballot_sync(0xFFFFFFFFu, valid && (lov != hiv));
            if (lane == 0) sEq[lr] = (unsigned char)(valid && (ne == 0));
        }
    }
    __syncthreads();
    if (w == 0) {
        bool f = (lane < NR) ? (sEq[lane] != 0) : false;
        unsigned msk = __ballot_sync(0xFFFFFFFFu, f);
        int conv = msk ? (r0 + __ffs(msk) - 1) : rend;
        if (lane == 0) g_conv[blk] = conv;
    }

    // ---- expansion: warp w expands rows 2w, 2w+1 from shared ----
    {
        #pragma unroll
        for (int rr = 0; rr < 2; ++rr) {
            int lr = 2 * w + rr;
            int r = r0 + lr;
            bool edge = (r == 0) || (r == H - 1);
            float4* orow = (float4*)out + (size_t)r * (WD / 4);
            #pragma unroll 1
            for (int g = 0; g < 16; ++g) {
                int wd = 2 * g + (lane >> 4);
                ull Sw = edge ? sS[(1 + lr) * 32 + wd] : sO[lr * 32 + wd];
                ull Wm = sW[(1 + lr) * 32 + wd];
                ull cm = (wd == 0 ? 1ULL : 0ULL) | (wd == 31 ? (1ULL << 63) : 0ULL);
                ull Ww = edge ? Wm : (Wm & cm);
                int bit = (lane & 15) * 4;
                unsigned snib = (unsigned)(Sw >> bit) & 0xFu;
                unsigned wnib = (unsigned)(Ww >> bit) & 0xFu;
                orow[g * 32 + lane] = nib2f4(snib, wnib);
            }
        }
    }

    // ---- last-block ticket ----
    __threadfence();            // release this block's writes
    __syncthreads();
    if (tid == 0) {
        unsigned t = atomicAdd(&g_tick, 1u);
        s_last = (t == GRID - 1) ? 1u : 0u;
    }
    __syncthreads();
    if (!s_last || w != 0) return;

    // ---- passB: fixup (last block, warp 0) + output rewrite ----
    __threadfence();            // acquire other blocks' writes
    unsigned need[GRID / 32];
    int myconv[GRID / 32];
    #pragma unroll
    for (int k = 0; k < GRID / 32; ++k) {
        int c = k * 32 + lane;
        int cv = g_conv[c];
        myconv[k] = cv;
        int rs = (c == 0) ? 1 : c * NR;
        need[k] = __ballot_sync(0xFFFFFFFFu, cv > rs);
    }
    ull s = 0;
    int prev_c = -2;
    bool prev_carry = false;
    const ull cmB = (lane == 0 ? 1ULL : 0ULL) | (lane == 31 ? (1ULL << 63) : 0ULL);
    #pragma unroll 1
    for (int k = 0; k < GRID / 32; ++k) {
        unsigned m = need[k];
        while (m) {
            int bit = __ffs(m) - 1;
            m &= m - 1;
            int c = k * 32 + bit;
            int rs = (c == 0) ? 1 : c * NR;
            int rendc = min(c * NR + NR, H - 1);
            int conv = __shfl_sync(0xFFFFFFFFu, myconv[k], bit);
            bool use_carry = prev_carry && (c == prev_c + 1);
            if (!use_carry)
                s = (c == 0) ? g_S0[lane] : g_O[(rs - 1) * WORDS + lane];
            for (int i = rs; i < conv; ++i) {
                ulonglong2 q = g_AW[i * WORDS + lane];
                s = row_step(s, q.x, q.y & bclear, lane);
                g_O[i * WORDS + lane] = s;
                // rewrite output for this corrected interior row
                ull Ww = q.y & cmB;
                float4* orow = (float4*)out + (size_t)i * (WD / 4) + lane * 16;
                #pragma unroll
                for (int j = 0; j < 16; ++j) {
                    unsigned snib = (unsigned)(s >> (j * 4)) & 0xFu;
                    unsigned wnib = (unsigned)(Ww >> (j * 4)) & 0xFu;
                    orow[j] = nib2f4(snib, wnib);
                }
            }
            prev_carry = (conv == rendc);
            prev_c = c;
        }
    }
    __syncwarp();
    if (lane == 0) { g_tick = 0; g_bar = 0; }   // reset for next launch (stream-ordered)
}

extern "C" void kernel_launch(void* const* d_in, const int* in_sizes, int n_in,
                              void* d_out, int out_size) {
    const float* img = (const float*)d_in[0];
    float* out = (float*)d_out;
    k_all<<<GRID, 256>>>(img, out);
}

// round 15
// speedup vs baseline: 1.0565x; 1.0565x over previous
#include <cuda_runtime.h>

#define H 2048
#define WD 2048
#define WORDS 32   // 2048 bits / 64 per lane
#define NR 4       // rows per block
#define GRID 512   // blocks: block blk owns rows 4*blk .. 4*blk+3
#define NC GRID    // chunk c = rows [4c, 4c+4) ∩ [1, H-2]

typedef unsigned long long ull;

// ---- persistent device scratch (no allocation allowed) ----
__device__ unsigned g_maxbits;            // zero at load; atomicMax idempotent per input
__device__ unsigned g_tick;               // last-block ticket; reset to 0 each launch by last block
__device__ unsigned g_bar;                // max-phase barrier counter; reset to 0 each launch by last block
__device__ ull g_S0[WORDS];               // strong mask of t, row 0 (passB seed)
__device__ ulonglong2 g_AW[H * WORDS];    // interleaved {a0, weak} for passB
__device__ ull g_O[H * WORDS];            // chunk-tail strong masks (passB seeds)
__device__ int g_conv[NC];                // first converged row per chunk

__device__ __forceinline__ unsigned enc(float f) {
    unsigned u = __float_as_uint(f);
    return (u & 0x80000000u) ? ~u : (u | 0x80000000u);
}
__device__ __forceinline__ float dec(unsigned u) {
    u = (u & 0x80000000u) ? (u & 0x7FFFFFFFu) : ~u;
    return __uint_as_float(u);
}

// One row-update step (warp-collective). b must already be interior-masked.
__device__ __forceinline__ ull row_step(ull s_prev, ull a0, ull b, int lane) {
    ull su = __shfl_up_sync(0xFFFFFFFFu, s_prev, 1);   if (lane == 0)  su = 0;
    ull sd = __shfl_down_sync(0xFFFFFFFFu, s_prev, 1); if (lane == 31) sd = 0;
    ull spread = s_prev | (s_prev << 1) | (su >> 63) | (s_prev >> 1) | (sd << 63);
    ull a = a0 | (b & spread);
    ull X = a | b;
    ull S0 = X + a;
    ull S1 = S0 + 1;
    bool Gw = S0 < X;
    bool Pw = (S0 == ~0ULL);
    unsigned gg = __ballot_sync(0xFFFFFFFFu, Gw);
    unsigned pp = __ballot_sync(0xFFFFFFFFu, Pw);
    ull c0 = S0 ^ X ^ a;
    ull c1 = S1 ^ X ^ a;
    ull out0 = (c0 >> 1) | ((ull)Gw << 63);
    ull out1 = (c1 >> 1) | ((ull)(Gw | Pw) << 63);
    unsigned Xr = gg | pp;
    unsigned Sr = Xr + gg;
    unsigned cr = Sr ^ Xr ^ gg;             // bit w = carry INTO word w
    unsigned cin = (cr >> lane) & 1u;
    return cin ? out1 : out0;
}

// Expand a 4-bit strong/weak nibble pair into a float4.
__device__ __forceinline__ float4 nib2f4(unsigned snib, unsigned wnib) {
    float4 v;
    v.x = (snib & 1u) ? 255.0f : ((wnib & 1u) ? 25.0f : 0.0f);
    v.y = (snib & 2u) ? 255.0f : ((wnib & 2u) ? 25.0f : 0.0f);
    v.z = (snib & 4u) ? 255.0f : ((wnib & 4u) ? 25.0f : 0.0f);
    v.w = (snib & 8u) ? 255.0f : ((wnib & 8u) ? 25.0f : 0.0f);
    return v;
}

// Single fused kernel: 8 warps/block, each row split across 2 warps for the
// latency-bound phases.
__global__ void __launch_bounds__(256) k_all(const float* __restrict__ x,
                                             float* __restrict__ out) {
    __shared__ ull sS[(NR + 2) * 32];  // sS[0]=row r0-1, sS[1+lr]=row r0+lr, sS[NR+1]=row r0+NR
    __shared__ ull sW[(NR + 1) * 32];  // sW[0]=row r0-1, sW[1+lr]=row r0+lr
    __shared__ ull sA[NR * 32];        // A0 of rows r0..r0+NR-1
    __shared__ ull sO[NR * 32];        // lo chain (speculative new strong)
    __shared__ ull sHi[NR * 32];       // hi chain
    __shared__ unsigned char sEq[NR];  // per-row lo==hi flags
    __shared__ float sred[8];
    __shared__ unsigned s_last;
    const int tid = threadIdx.x;
    const int w = tid >> 5;
    const int lane = tid & 31;
    const int blk = blockIdx.x;
    const int r0 = blk * NR;

    // ---- phase 0: coalesced DRAM read + block max + grid barrier ----
    {
        const float4* x4 = (const float4*)x + (size_t)blk * (NR * WD / 4);  // 2048 float4
        float m0 = 0.0f, m1 = 0.0f, m2 = 0.0f, m3 = 0.0f;                   // inputs uniform [0,1)
        #pragma unroll
        for (int it = 0; it < 2; ++it) {
            float4 v0 = x4[tid + (it * 4 + 0) * 256];
            float4 v1 = x4[tid + (it * 4 + 1) * 256];
            float4 v2 = x4[tid + (it * 4 + 2) * 256];
            float4 v3 = x4[tid + (it * 4 + 3) * 256];
            m0 = fmaxf(m0, fmaxf(fmaxf(v0.x, v0.y), fmaxf(v0.z, v0.w)));
            m1 = fmaxf(m1, fmaxf(fmaxf(v1.x, v1.y), fmaxf(v1.z, v1.w)));
            m2 = fmaxf(m2, fmaxf(fmaxf(v2.x, v2.y), fmaxf(v2.z, v2.w)));
            m3 = fmaxf(m3, fmaxf(fmaxf(v3.x, v3.y), fmaxf(v3.z, v3.w)));
        }
        float m = fmaxf(fmaxf(m0, m1), fmaxf(m2, m3));
        #pragma unroll
        for (int o = 16; o > 0; o >>= 1)
            m = fmaxf(m, __shfl_xor_sync(0xFFFFFFFFu, m, o));
        if (lane == 0) sred[w] = m;
        __syncthreads();
        if (tid == 0) {
            float mm = sred[0];
            #pragma unroll
            for (int k = 1; k < 8; ++k) mm = fmaxf(mm, sred[k]);
            atomicMax(&g_maxbits, enc(mm));
            __threadfence();
            atomicAdd(&g_bar, 1u);
            unsigned v;
            do {
                asm volatile("ld.acquire.gpu.global.u32 %0, [%1];" : "=r"(v) : "l"(&g_bar) : "memory");
                if (v >= GRID) break;
                __nanosleep(32);
            } while (true);
            unsigned mb;
            asm volatile("ld.acquire.gpu.global.u32 %0, [%1];" : "=r"(mb) : "l"(&g_maxbits) : "memory");
            sred[0] = dec(mb);
        }
        __syncthreads();
    }
    const float high = sred[0] * 0.15f;
    const float low = high * 0.05f;

    // ---- mask phase: warp w -> row (w>>1), words (w&1)*16 .. +15 (L2-hot) ----
    {
        int lr = w >> 1;
        int h = w & 1;
        int r = r0 + lr;
        const float* rowp = x + (size_t)r * WD;
        #pragma unroll 1
        for (int j = 0; j < 16; ++j) {
            int wd = h * 16 + j;
            float a = rowp[wd * 64 + lane];
            float b2 = rowp[wd * 64 + 32 + lane];
            unsigned slo = __ballot_sync(0xFFFFFFFFu, a > high);
            unsigned shi = __ballot_sync(0xFFFFFFFFu, b2 > high);
            unsigned wlo = __ballot_sync(0xFFFFFFFFu, (a >= low) && (a <= high));
            unsigned whi = __ballot_sync(0xFFFFFFFFu, (b2 >= low) && (b2 <= high));
            if (lane == 0) {
                ull S = (ull)slo | ((ull)shi << 32);
                ull Wm = (ull)wlo | ((ull)whi << 32);
                sS[(1 + lr) * 32 + wd] = S;
                sW[(1 + lr) * 32 + wd] = Wm;
                if (r == 0) g_S0[wd] = S;          // passB seed (block 0 only)
            }
        }
        if (blk > 0 && w < 4) {                    // boundary row r0-1: S and W
            const float* rm = x + (size_t)(r0 - 1) * WD;
            #pragma unroll
            for (int j = 0; j < 8; ++j) {
                int wd = w * 8 + j;
                float a = rm[wd * 64 + lane];
                float b2 = rm[wd * 64 + 32 + lane];
                unsigned slo = __ballot_sync(0xFFFFFFFFu, a > high);
                unsigned shi = __ballot_sync(0xFFFFFFFFu, b2 > high);
                unsigned wlo = __ballot_sync(0xFFFFFFFFu, (a >= low) && (a <= high));
                unsigned whi = __ballot_sync(0xFFFFFFFFu, (b2 >= low) && (b2 <= high));
                if (lane == 0) {
                    sS[wd] = (ull)slo | ((ull)shi << 32);
                    sW[wd] = (ull)wlo | ((ull)whi << 32);
                }
            }
        }
        if (blk < GRID - 1 && w >= 4) {            // boundary row r0+NR: S only
            const float* rp = x + (size_t)(r0 + NR) * WD;
            #pragma unroll
            for (int j = 0; j < 8; ++j) {
                int wd = (w - 4) * 8 + j;
                float a = rp[wd * 64 + lane];
                float b2 = rp[wd * 64 + 32 + lane];
                unsigned slo = __ballot_sync(0xFFFFFFFFu, a > high);
                unsigned shi = __ballot_sync(0xFFFFFFFFu, b2 > high);
                if (lane == 0) sS[(NR + 1) * 32 + wd] = (ull)slo | ((ull)shi << 32);
            }
        }
    }
    __syncthreads();

    // ---- A0 phase: warps 0..3 -> row w (interior only), shfl neighbors ----
    if (w < 4) {
        int i = r0 + w;
        if (i >= 1 && i <= H - 2) {
            ull cs = sS[(1 + w) * 32 + lane];
            ull ns = sS[(2 + w) * 32 + lane];
            ull wk = sW[(1 + w) * 32 + lane];
            ull wkI = wk;
            if (lane == 0)  wkI &= ~1ULL;
            if (lane == 31) wkI &= 0x7FFFFFFFFFFFFFFFULL;
            ull cs_n = __shfl_down_sync(0xFFFFFFFFu, cs, 1); if (lane == 31) cs_n = 0;
            ull ns_n = __shfl_down_sync(0xFFFFFFFFu, ns, 1); if (lane == 31) ns_n = 0;
            ull ns_p = __shfl_up_sync(0xFFFFFFFFu, ns, 1);   if (lane == 0)  ns_p = 0;
            ull shl_cs = (cs >> 1) | (cs_n << 63);
            ull shl_ns = (ns >> 1) | (ns_n << 63);
            ull shr_ns = (ns << 1) | (ns_p >> 63);
            ull base0 = shl_cs | shr_ns | ns | shl_ns;
            ull a0v = cs | (wkI & base0);
            sA[w * 32 + lane] = a0v;
            ulonglong2 v; v.x = a0v; v.y = wk;
            g_AW[i * WORDS + lane] = v;
        }
    }
    __syncthreads();

    ull bclear = ~0ULL;
    if (lane == 0)  bclear = ~1ULL;
    if (lane == 31) bclear = 0x7FFFFFFFFFFFFFFFULL;

    const int rstart = (blk == 0) ? 1 : r0;
    const int rend = min(r0 + NR, H - 1);

    // ---- passA: lo chain in warp 0, hi chain in warp 1 (independent) ----
    if (w <= 1) {
        bool isLo = (w == 0);
        ull s;
        if (blk == 0) s = sS[32 + lane];                             // row 0 exact
        else s = isLo ? sS[lane] : (sS[lane] | (sW[lane] & bclear)); // bounds of row r0-1
        #pragma unroll 1
        for (int i = rstart; i < rend; ++i) {
            ull a0 = sA[(i - r0) * 32 + lane];
            ull b = sW[(1 + i - r0) * 32 + lane] & bclear;
            s = row_step(s, a0, b, lane);
            if (isLo) {
                sO[(i - r0) * 32 + lane] = s;
                if (i == rend - 1) g_O[i * WORDS + lane] = s;  // only seed row needed
            } else {
                sHi[(i - r0) * 32 + lane] = s;
            }
        }
    }
    __syncthreads();

    // ---- conv detection: warps 0..3 check row w; warp 0 reduces ----
    if (w < 4) {
        int i = r0 + w;
        bool valid = (i >= rstart) && (i < rend);
        ull lov = sO[w * 32 + lane];
        ull hiv = sHi[w * 32 + lane];
        unsigned ne = __ballot_sync(0xFFFFFFFFu, valid && (lov != hiv));
        if (lane == 0) sEq[w] = (unsigned char)(valid && (ne == 0));
    }
    __syncthreads();
    if (w == 0) {
        bool f = (lane < NR) ? (sEq[lane] != 0) : false;
        unsigned msk = __ballot_sync(0xFFFFFFFFu, f);
        int conv = msk ? (r0 + __ffs(msk) - 1) : rend;
        if (lane == 0) g_conv[blk] = conv;
    }

    // ---- expansion: warp w expands row (w>>1), half (w&1) from shared ----
    {
        int lr = w >> 1;
        int h = w & 1;
        int r = r0 + lr;
        bool edge = (r == 0) || (r == H - 1);
        float4* orow = (float4*)out + (size_t)r * (WD / 4) + h * 256;
        #pragma unroll 1
        for (int g = 0; g < 8; ++g) {
            int wd = h * 16 + 2 * g + (lane >> 4);
            ull Sw = edge ? sS[(1 + lr) * 32 + wd] : sO[lr * 32 + wd];
            ull Wm = sW[(1 + lr) * 32 + wd];
            ull cm = (wd == 0 ? 1ULL : 0ULL) | (wd == 31 ? (1ULL << 63) : 0ULL);
            ull Ww = edge ? Wm : (Wm & cm);
            int bit = (lane & 15) * 4;
            unsigned snib = (unsigned)(Sw >> bit) & 0xFu;
            unsigned wnib = (unsigned)(Ww >> bit) & 0xFu;
            orow[g * 32 + lane] = nib2f4(snib, wnib);
        }
    }

    // ---- last-block ticket ----
    __threadfence();            // release this block's writes
    __syncthreads();
    if (tid == 0) {
        unsigned t = atomicAdd(&g_tick, 1u);
        s_last = (t == GRID - 1) ? 1u : 0u;
    }
    __syncthreads();
    if (!s_last || w != 0) return;

    // ---- passB: fixup (last block, warp 0) + output rewrite ----
    __threadfence();            // acquire other blocks' writes
    unsigned need[GRID / 32];
    int myconv[GRID / 32];
    #pragma unroll
    for (int k = 0; k < GRID / 32; ++k) {
        int c = k * 32 + lane;
        int cv = g_conv[c];
        myconv[k] = cv;
        int rs = (c == 0) ? 1 : c * NR;
        need[k] = __ballot_sync(0xFFFFFFFFu, cv > rs);
    }
    ull s = 0;
    int prev_c = -2;
    bool prev_carry = false;
    const ull cmB = (lane == 0 ? 1ULL : 0ULL) | (lane == 31 ? (1ULL << 63) : 0ULL);
    #pragma unroll 1
    for (int k = 0; k < GRID / 32; ++k) {
        unsigned m = need[k];
        while (m) {
            int bit = __ffs(m) - 1;
            m &= m - 1;
            int c = k * 32 + bit;
            int rs = (c == 0) ? 1 : c * NR;
            int rendc = min(c * NR + NR, H - 1);
            int conv = __shfl_sync(0xFFFFFFFFu, myconv[k], bit);
            bool use_carry = prev_carry && (c == prev_c + 1);
            if (!use_carry)
                s = (c == 0) ? g_S0[lane] : g_O[(rs - 1) * WORDS + lane];
            for (int i = rs; i < conv; ++i) {
                ulonglong2 q = g_AW[i * WORDS + lane];
                s = row_step(s, q.x, q.y & bclear, lane);
                g_O[i * WORDS + lane] = s;
                // rewrite output for this corrected interior row
                ull Ww = q.y & cmB;
                float4* orow = (float4*)out + (size_t)i * (WD / 4) + lane * 16;
                #pragma unroll
                for (int j = 0; j < 16; ++j) {
                    unsigned snib = (unsigned)(s >> (j * 4)) & 0xFu;
                    unsigned wnib = (unsigned)(Ww >> (j * 4)) & 0xFu;
                    orow[j] = nib2f4(snib, wnib);
                }
            }
            prev_carry = (conv == rendc);
            prev_c = c;
        }
    }
    __syncwarp();
    if (lane == 0) { g_tick = 0; g_bar = 0; }   // reset for next launch (stream-ordered)
}

extern "C" void kernel_launch(void* const* d_in, const int* in_sizes, int n_in,
                              void* d_out, int out_size) {
    const float* img = (const float*)d_in[0];
    float* out = (float*)d_out;
    k_all<<<GRID, 256>>>(img, out);
}

// round 16
// speedup vs baseline: 1.1064x; 1.0473x over previous
#include <cuda_runtime.h>

#define H 2048
#define WD 2048
#define WORDS 32   // 2048 bits / 64 per lane
#define NR 4       // rows per block
#define GRID 512   // blocks: block blk owns rows 4*blk .. 4*blk+3
#define NC GRID    // chunk c = rows [4c, 4c+4) ∩ [1, H-2]

typedef unsigned long long ull;

// ---- persistent device scratch (no allocation allowed) ----
__device__ unsigned g_maxbits;            // zero at load; atomicMax idempotent per input
__device__ unsigned g_tick;               // last-block ticket; reset to 0 each launch by last block
__device__ unsigned g_bar;                // max-phase barrier counter; reset to 0 each launch by last block
__device__ ull g_S0[WORDS];               // strong mask of t, row 0 (passB seed)
__device__ ulonglong2 g_AW[H * WORDS];    // interleaved {a0, weak} for passB
__device__ ull g_O[H * WORDS];            // new strong masks (rows 1..H-2), passB seeds/fixup
__device__ int g_conv[NC];                // first converged row per chunk

__device__ __forceinline__ unsigned enc(float f) {
    unsigned u = __float_as_uint(f);
    return (u & 0x80000000u) ? ~u : (u | 0x80000000u);
}
__device__ __forceinline__ float dec(unsigned u) {
    u = (u & 0x80000000u) ? (u & 0x7FFFFFFFu) : ~u;
    return __uint_as_float(u);
}

__device__ __forceinline__ float max4(float4 v) {
    return fmaxf(fmaxf(v.x, v.y), fmaxf(v.z, v.w));
}

// One row-update step (warp-collective). b must already be interior-masked.
__device__ __forceinline__ ull row_step(ull s_prev, ull a0, ull b, int lane) {
    ull su = __shfl_up_sync(0xFFFFFFFFu, s_prev, 1);   if (lane == 0)  su = 0;
    ull sd = __shfl_down_sync(0xFFFFFFFFu, s_prev, 1); if (lane == 31) sd = 0;
    ull spread = s_prev | (s_prev << 1) | (su >> 63) | (s_prev >> 1) | (sd << 63);
    ull a = a0 | (b & spread);
    ull X = a | b;
    ull S0 = X + a;
    ull S1 = S0 + 1;
    bool Gw = S0 < X;
    bool Pw = (S0 == ~0ULL);
    unsigned gg = __ballot_sync(0xFFFFFFFFu, Gw);
    unsigned pp = __ballot_sync(0xFFFFFFFFu, Pw);
    ull c0 = S0 ^ X ^ a;
    ull c1 = S1 ^ X ^ a;
    ull out0 = (c0 >> 1) | ((ull)Gw << 63);
    ull out1 = (c1 >> 1) | ((ull)(Gw | Pw) << 63);
    unsigned Xr = gg | pp;
    unsigned Sr = Xr + gg;
    unsigned cr = Sr ^ Xr ^ gg;             // bit w = carry INTO word w
    unsigned cin = (cr >> lane) & 1u;
    return cin ? out1 : out0;
}

// Expand a 4-bit strong/weak nibble pair into a float4.
__device__ __forceinline__ float4 nib2f4(unsigned snib, unsigned wnib) {
    float4 v;
    v.x = (snib & 1u) ? 255.0f : ((wnib & 1u) ? 25.0f : 0.0f);
    v.y = (snib & 2u) ? 255.0f : ((wnib & 2u) ? 25.0f : 0.0f);
    v.z = (snib & 4u) ? 255.0f : ((wnib & 4u) ? 25.0f : 0.0f);
    v.w = (snib & 8u) ? 255.0f : ((wnib & 8u) ? 25.0f : 0.0f);
    return v;
}

// Single fused kernel: block-local max (front-batched loads, MLP=16) + one
// grid barrier + masks/A0 + passA + per-block expansion + last-block passB.
__global__ void __launch_bounds__(128) k_all(const float* __restrict__ x,
                                             float* __restrict__ out) {
    __shared__ ull sS[(NR + 2) * 32];  // sS[0]=row r0-1, sS[1+w]=row r0+w, sS[NR+1]=row r0+NR
    __shared__ ull sW[(NR + 1) * 32];  // sW[0]=row r0-1, sW[1+w]=row r0+w
    __shared__ ull sA[NR * 32];        // A0 of rows r0..r0+NR-1
    __shared__ ull sO[NR * 32];        // new strong of rows r0..r0+NR-1 (speculative lo)
    __shared__ float sred[NR];
    __shared__ unsigned s_last;
    const int tid = threadIdx.x;
    const int w = tid >> 5;
    const int lane = tid & 31;
    const int blk = blockIdx.x;
    const int r0 = blk * NR;

    // ---- phase 0: block max with 16 front-batched LDG.128 per thread ----
    {
        const float4* x4 = (const float4*)x + (size_t)blk * (NR * WD / 4);  // 2048 float4
        // all 16 loads issued before any consumer -> MLP = 16
        float4 v0 = x4[tid + 0 * 128],  v1 = x4[tid + 1 * 128];
        float4 v2 = x4[tid + 2 * 128],  v3 = x4[tid + 3 * 128];
        float4 v4 = x4[tid + 4 * 128],  v5 = x4[tid + 5 * 128];
        float4 v6 = x4[tid + 6 * 128],  v7 = x4[tid + 7 * 128];
        float4 v8 = x4[tid + 8 * 128],  v9 = x4[tid + 9 * 128];
        float4 va = x4[tid + 10 * 128], vb = x4[tid + 11 * 128];
        float4 vc = x4[tid + 12 * 128], vd = x4[tid + 13 * 128];
        float4 ve = x4[tid + 14 * 128], vf = x4[tid + 15 * 128];
        float m = fmaxf(
            fmaxf(fmaxf(fmaxf(max4(v0), max4(v1)), fmaxf(max4(v2), max4(v3))),
                  fmaxf(fmaxf(max4(v4), max4(v5)), fmaxf(max4(v6), max4(v7)))),
            fmaxf(fmaxf(fmaxf(max4(v8), max4(v9)), fmaxf(max4(va), max4(vb))),
                  fmaxf(fmaxf(max4(vc), max4(vd)), fmaxf(max4(ve), max4(vf)))));
        #pragma unroll
        for (int o = 16; o > 0; o >>= 1)
            m = fmaxf(m, __shfl_xor_sync(0xFFFFFFFFu, m, o));
        if (lane == 0) sred[w] = m;
        __syncthreads();
        if (tid == 0) {
            float mm = fmaxf(fmaxf(sred[0], sred[1]), fmaxf(sred[2], sred[3]));
            atomicMax(&g_maxbits, enc(mm));
            __threadfence();
            atomicAdd(&g_bar, 1u);
            unsigned v;
            do {
                asm volatile("ld.acquire.gpu.global.u32 %0, [%1];" : "=r"(v) : "l"(&g_bar) : "memory");
                if (v >= GRID) break;
                __nanosleep(32);
            } while (true);
            unsigned mb;
            asm volatile("ld.acquire.gpu.global.u32 %0, [%1];" : "=r"(mb) : "l"(&g_maxbits) : "memory");
            sred[0] = dec(mb);
        }
        __syncthreads();
    }
    const float high = sred[0] * 0.15f;
    const float low = high * 0.05f;

    // ---- mask phase: warp w -> owned row r0+w (image is L2-hot) ----
    {
        int r = r0 + w;
        const float* rowp = x + (size_t)r * WD;
        for (int wd = 0; wd < 32; ++wd) {
            float a = rowp[wd * 64 + lane];
            float b2 = rowp[wd * 64 + 32 + lane];
            unsigned slo = __ballot_sync(0xFFFFFFFFu, a > high);
            unsigned shi = __ballot_sync(0xFFFFFFFFu, b2 > high);
            unsigned wlo = __ballot_sync(0xFFFFFFFFu, (a >= low) && (a <= high));
            unsigned whi = __ballot_sync(0xFFFFFFFFu, (b2 >= low) && (b2 <= high));
            if (lane == 0) {
                ull S = (ull)slo | ((ull)shi << 32);
                ull Wm = (ull)wlo | ((ull)whi << 32);
                sS[(1 + w) * 32 + wd] = S;
                sW[(1 + w) * 32 + wd] = Wm;
                if (r == 0) g_S0[wd] = S;          // passB seed (block 0 only)
            }
        }
        if (blk > 0) {                             // boundary row r0-1: S and W
            const float* rm = x + (size_t)(r0 - 1) * WD;
            #pragma unroll
            for (int j = 0; j < 8; ++j) {
                int wd = w * 8 + j;
                float a = rm[wd * 64 + lane];
                float b2 = rm[wd * 64 + 32 + lane];
                unsigned slo = __ballot_sync(0xFFFFFFFFu, a > high);
                unsigned shi = __ballot_sync(0xFFFFFFFFu, b2 > high);
                unsigned wlo = __ballot_sync(0xFFFFFFFFu, (a >= low) && (a <= high));
                unsigned whi = __ballot_sync(0xFFFFFFFFu, (b2 >= low) && (b2 <= high));
                if (lane == 0) {
                    sS[wd] = (ull)slo | ((ull)shi << 32);
                    sW[wd] = (ull)wlo | ((ull)whi << 32);
                }
            }
        }
        if (blk < GRID - 1) {                      // boundary row r0+NR: S only
            const float* rp = x + (size_t)(r0 + NR) * WD;
            #pragma unroll
            for (int j = 0; j < 8; ++j) {
                int wd = w * 8 + j;
                float a = rp[wd * 64 + lane];
                float b2 = rp[wd * 64 + 32 + lane];
                unsigned slo = __ballot_sync(0xFFFFFFFFu, a > high);
                unsigned shi = __ballot_sync(0xFFFFFFFFu, b2 > high);
                if (lane == 0) sS[(NR + 1) * 32 + wd] = (ull)slo | ((ull)shi << 32);
            }
        }
    }
    __syncthreads();

    // ---- A0 phase: warp w -> row i = r0+w (interior only) ----
    {
        int i = r0 + w;
        if (i >= 1 && i <= H - 2) {
            ull cs = sS[(1 + w) * 32 + lane];
            ull ns = sS[(2 + w) * 32 + lane];
            ull wk = sW[(1 + w) * 32 + lane];
            ull wkI = wk;
            if (lane == 0)  wkI &= ~1ULL;
            if (lane == 31) wkI &= 0x7FFFFFFFFFFFFFFFULL;
            ull cs_n = __shfl_down_sync(0xFFFFFFFFu, cs, 1); if (lane == 31) cs_n = 0;
            ull ns_n = __shfl_down_sync(0xFFFFFFFFu, ns, 1); if (lane == 31) ns_n = 0;
            ull ns_p = __shfl_up_sync(0xFFFFFFFFu, ns, 1);   if (lane == 0)  ns_p = 0;
            ull shl_cs = (cs >> 1) | (cs_n << 63);
            ull shl_ns = (ns >> 1) | (ns_n << 63);
            ull shr_ns = (ns << 1) | (ns_p >> 63);
            ull base0 = shl_cs | shr_ns | ns | shl_ns;
            ull a0v = cs | (wkI & base0);
            sA[w * 32 + lane] = a0v;
            ulonglong2 v; v.x = a0v; v.y = wk;
            g_AW[i * WORDS + lane] = v;
        }
    }
    __syncthreads();

    ull bclear = ~0ULL;
    if (lane == 0)  bclear = ~1ULL;
    if (lane == 31) bclear = 0x7FFFFFFFFFFFFFFFULL;

    // ---- passA: warp 0, chunk = blk, operands in shared; keep lo in sO ----
    if (w == 0) {
        int rstart = (blk == 0) ? 1 : r0;
        int rend = min(r0 + NR, H - 1);
        ull lo, hi;
        if (blk == 0) { lo = sS[32 + lane]; hi = lo; }               // row 0 exact
        else { lo = sS[lane]; hi = lo | (sW[lane] & bclear); }       // row r0-1 bounds
        int conv = rend;
        #pragma unroll 1
        for (int i = rstart; i < rend; ++i) {
            ull a0 = sA[(i - r0) * 32 + lane];
            ull b = sW[(1 + i - r0) * 32 + lane] & bclear;
            lo = row_step(lo, a0, b, lane);
            hi = row_step(hi, a0, b, lane);
            sO[(i - r0) * 32 + lane] = lo;
            g_O[i * WORDS + lane] = lo;
            unsigned ne = __ballot_sync(0xFFFFFFFFu, lo != hi);
            if (ne == 0 && conv == rend) conv = i;
        }
        if (lane == 0) g_conv[blk] = conv;
    }
    __syncthreads();

    // ---- expansion: warp w expands its own row r0+w from shared ----
    {
        int r = r0 + w;
        bool edge = (r == 0) || (r == H - 1);
        float4* orow = (float4*)out + (size_t)r * (WD / 4);
        #pragma unroll 1
        for (int g = 0; g < 16; ++g) {
            int wd = 2 * g + (lane >> 4);
            ull Sw = edge ? sS[(1 + w) * 32 + wd] : sO[w * 32 + wd];
            ull Wm = sW[(1 + w) * 32 + wd];
            ull cm = (wd == 0 ? 1ULL : 0ULL) | (wd == 31 ? (1ULL << 63) : 0ULL);
            ull Ww = edge ? Wm : (Wm & cm);
            int bit = (lane & 15) * 4;
            unsigned snib = (unsigned)(Sw >> bit) & 0xFu;
            unsigned wnib = (unsigned)(Ww >> bit) & 0xFu;
            orow[g * 32 + lane] = nib2f4(snib, wnib);
        }
    }

    // ---- last-block ticket ----
    __threadfence();            // release this block's writes
    __syncthreads();
    if (tid == 0) {
        unsigned t = atomicAdd(&g_tick, 1u);
        s_last = (t == GRID - 1) ? 1u : 0u;
    }
    __syncthreads();
    if (!s_last || w != 0) return;

    // ---- passB: fixup (last block, warp 0) + output rewrite ----
    __threadfence();            // acquire other blocks' writes
    unsigned need[GRID / 32];
    int myconv[GRID / 32];
    #pragma unroll
    for (int k = 0; k < GRID / 32; ++k) {
        int c = k * 32 + lane;
        int cv = g_conv[c];
        myconv[k] = cv;
        int rs = (c == 0) ? 1 : c * NR;
        need[k] = __ballot_sync(0xFFFFFFFFu, cv > rs);
    }
    ull s = 0;
    int prev_c = -2;
    bool prev_carry = false;
    const ull cmB = (lane == 0 ? 1ULL : 0ULL) | (lane == 31 ? (1ULL << 63) : 0ULL);
    #pragma unroll 1
    for (int k = 0; k < GRID / 32; ++k) {
        unsigned m = need[k];
        while (m) {
            int bit = __ffs(m) - 1;
            m &= m - 1;
            int c = k * 32 + bit;
            int rs = (c == 0) ? 1 : c * NR;
            int rend = min(c * NR + NR, H - 1);
            int conv = __shfl_sync(0xFFFFFFFFu, myconv[k], bit);
            bool use_carry = prev_carry && (c == prev_c + 1);
            if (!use_carry)
                s = (c == 0) ? g_S0[lane] : g_O[(rs - 1) * WORDS + lane];
            for (int i = rs; i < conv; ++i) {
                ulonglong2 q = g_AW[i * WORDS + lane];
                s = row_step(s, q.x, q.y & bclear, lane);
                g_O[i * WORDS + lane] = s;
                // rewrite output for this corrected interior row
                ull Ww = q.y & cmB;
                float4* orow = (float4*)out + (size_t)i * (WD / 4) + lane * 16;
                #pragma unroll
                for (int j = 0; j < 16; ++j) {
                    unsigned snib = (unsigned)(s >> (j * 4)) & 0xFu;
                    unsigned wnib = (unsigned)(Ww >> (j * 4)) & 0xFu;
                    orow[j] = nib2f4(snib, wnib);
                }
            }
            prev_carry = (conv == rend);
            prev_c = c;
        }
    }
    __syncwarp();
    if (lane == 0) { g_tick = 0; g_bar = 0; }   // reset for next launch (stream-ordered)
}

extern "C" void kernel_launch(void* const* d_in, const int* in_sizes, int n_in,
                              void* d_out, int out_size) {
    const float* img = (const float*)d_in[0];
    float* out = (float*)d_out;
    k_all<<<GRID, 128>>>(img, out);
}